// round 1
// baseline (speedup 1.0000x reference)
#include <cuda_runtime.h>
#include <cuda_bf16.h>

#define N_MAX    50000
#define E_MAX    1600000
#define HEADS    8
#define HD       32
#define FDIM     256          // HEADS*HD == F_IN == HID
#define SLOPE    0.2f
#define LN_EPS   1e-5f

// ---------------- scratch (device globals; no allocation allowed) ----------
__device__ float    g_H   [N_MAX * FDIM];   // h per node, [n][head*32+d]
__device__ float    g_si  [N_MAX * HEADS];
__device__ float    g_sj  [N_MAX * HEADS];
__device__ unsigned g_m   [N_MAX * HEADS];  // encoded segment max
__device__ float    g_den [N_MAX * HEADS];
__device__ float    g_e   [E_MAX * HEADS];  // edge scores, then exp values
__device__ float    g_agg [N_MAX * FDIM];
__device__ float    g_mean[N_MAX * HD];

// monotone float<->uint encoding for atomicMax on floats (incl. negatives)
__device__ __forceinline__ unsigned fenc(float f) {
    unsigned u = __float_as_uint(f);
    return (u & 0x80000000u) ? ~u : (u | 0x80000000u);
}
__device__ __forceinline__ float fdec(unsigned u) {
    return (u & 0x80000000u) ? __uint_as_float(u ^ 0x80000000u)
                             : __uint_as_float(~u);
}

// ---------------- K0: zero scratch -----------------------------------------
__global__ void k_init(int N) {
    int i = blockIdx.x * 256 + threadIdx.x;
    if (i < N * FDIM) g_agg[i] = 0.f;
    if (i < N * HEADS) { g_den[i] = 0.f; g_m[i] = 0u; }
}

// ---------------- K1: H = X @ Wf + bw  (128x128x16 tiled fp32 GEMM) --------
// Wf[k][c] = W[(c>>5)*F_IN*HD + k*HD + (c&31)],  c = head*32 + d
__global__ void __launch_bounds__(256)
k_gemm_h(const float* __restrict__ X, const float* __restrict__ W,
         const float* __restrict__ bw, int N) {
    __shared__ float As[16][132];
    __shared__ float Bs[16][132];
    const int tid  = threadIdx.x;
    const int row0 = blockIdx.y * 128;
    const int col0 = blockIdx.x * 128;
    const int tr   = (tid >> 4) * 8;
    const int tcb  = (tid & 15) * 8;

    float acc[8][8];
#pragma unroll
    for (int i = 0; i < 8; i++)
#pragma unroll
        for (int j = 0; j < 8; j++) acc[i][j] = 0.f;

    for (int k0 = 0; k0 < FDIM; k0 += 16) {
        // load X tile: 128 rows x 16 k  (512 float4, 2 per thread)
#pragma unroll
        for (int it = 0; it < 2; it++) {
            int v = tid + 256 * it;
            int r = v >> 2, kk = (v & 3) << 2;
            float4 xv = make_float4(0.f, 0.f, 0.f, 0.f);
            if (row0 + r < N)
                xv = *(const float4*)&X[(size_t)(row0 + r) * FDIM + k0 + kk];
            As[kk + 0][r] = xv.x; As[kk + 1][r] = xv.y;
            As[kk + 2][r] = xv.z; As[kk + 3][r] = xv.w;
        }
        // load W tile: 16 k x 128 c  (512 float4, 2 per thread)
#pragma unroll
        for (int it = 0; it < 2; it++) {
            int v = tid + 256 * it;
            int k = v >> 5, c4 = (v & 31) << 2;
            int c = col0 + c4;
            const float4 wv = *(const float4*)
                &W[(size_t)(c >> 5) * FDIM * HD + (size_t)(k0 + k) * HD + (c & 31)];
            *(float4*)&Bs[k][c4] = wv;
        }
        __syncthreads();
#pragma unroll
        for (int kk = 0; kk < 16; kk++) {
            float a[8], b[8];
            *(float4*)&a[0] = *(const float4*)&As[kk][tr];
            *(float4*)&a[4] = *(const float4*)&As[kk][tr + 4];
            *(float4*)&b[0] = *(const float4*)&Bs[kk][tcb];
            *(float4*)&b[4] = *(const float4*)&Bs[kk][tcb + 4];
#pragma unroll
            for (int i = 0; i < 8; i++)
#pragma unroll
                for (int j = 0; j < 8; j++) acc[i][j] += a[i] * b[j];
        }
        __syncthreads();
    }
    // epilogue: + bw, store
#pragma unroll
    for (int i = 0; i < 8; i++) {
        int row = row0 + tr + i;
        if (row >= N) break;
#pragma unroll
        for (int j = 0; j < 8; j++) {
            int c = col0 + tcb + j;
            g_H[(size_t)row * FDIM + c] = acc[i][j] + bw[c];
        }
    }
}

// ---------------- K2: si/sj per (node, head) — warp per head ---------------
__global__ void k_scores(const float* __restrict__ A, int N) {
    int n = blockIdx.x;
    if (n >= N) return;
    int h    = threadIdx.x >> 5;
    int lane = threadIdx.x & 31;
    float x  = g_H[(size_t)n * FDIM + h * HD + lane];
    float s1 = x * A[h * 2 * HD + lane];
    float s2 = x * A[h * 2 * HD + HD + lane];
#pragma unroll
    for (int o = 16; o; o >>= 1) {
        s1 += __shfl_xor_sync(0xffffffffu, s1, o);
        s2 += __shfl_xor_sync(0xffffffffu, s2, o);
    }
    if (lane == 0) {
        g_si[n * HEADS + h] = s1;
        g_sj[n * HEADS + h] = s2;
    }
}

// ---------------- K3: edge scores + segment max -----------------------------
__global__ void k_edge_max(const int* __restrict__ EI,
                           const float* __restrict__ ba, int E) {
    int gid = blockIdx.x * 256 + threadIdx.x;
    if (gid >= E * HEADS) return;
    int e = gid >> 3, h = gid & 7;
    int tgt = EI[e], src = EI[E + e];
    float sc = g_si[tgt * HEADS + h] + g_sj[src * HEADS + h] + ba[h];
    sc = (sc >= 0.f) ? sc : SLOPE * sc;
    g_e[gid] = sc;
    atomicMax(&g_m[tgt * HEADS + h], fenc(sc));
}

// ---------------- K4: exp + segment sum -------------------------------------
__global__ void k_edge_exp(const int* __restrict__ EI, int E) {
    int gid = blockIdx.x * 256 + threadIdx.x;
    if (gid >= E * HEADS) return;
    int e = gid >> 3, h = gid & 7;
    int tgt = EI[e];
    float m  = fdec(g_m[tgt * HEADS + h]);
    float ex = expf(g_e[gid] - m);
    g_e[gid] = ex;
    atomicAdd(&g_den[tgt * HEADS + h], ex);
}

// ---------------- K5: weighted message scatter (warp per edge) --------------
__global__ void k_edge_agg(const int* __restrict__ EI, int E) {
    int widx = (blockIdx.x * 256 + threadIdx.x) >> 5;
    if (widx >= E) return;
    int lane = threadIdx.x & 31;
    int tgt = EI[widx], src = EI[E + widx];
    int h0 = lane >> 3;                                   // head for first half
    float a0 = g_e[(size_t)widx * 8 + h0]     / g_den[tgt * HEADS + h0];
    float a1 = g_e[(size_t)widx * 8 + h0 + 4] / g_den[tgt * HEADS + h0 + 4];
    const float4* hs = (const float4*)&g_H[(size_t)src * FDIM];
    float4 v0 = hs[lane];       // channels lane*4..+3       (head = lane>>3)
    float4 v1 = hs[32 + lane];  // channels 128+lane*4..+3   (head = 4+lane>>3)
    float4* ag = (float4*)&g_agg[(size_t)tgt * FDIM];
    asm volatile("red.global.add.v4.f32 [%0], {%1,%2,%3,%4};"
                 :: "l"(ag + lane),
                    "f"(a0 * v0.x), "f"(a0 * v0.y), "f"(a0 * v0.z), "f"(a0 * v0.w)
                 : "memory");
    asm volatile("red.global.add.v4.f32 [%0], {%1,%2,%3,%4};"
                 :: "l"(ag + 32 + lane),
                    "f"(a1 * v1.x), "f"(a1 * v1.y), "f"(a1 * v1.z), "f"(a1 * v1.w)
                 : "memory");
}

// ---------------- K6: skip + ELU + LayerNorm + head-mean --------------------
__global__ void k_node(const float* __restrict__ gamma,
                       const float* __restrict__ beta, int N) {
    int n = blockIdx.x;
    if (n >= N) return;
    int c    = threadIdx.x;           // head*32 + d
    int lane = c & 31;
    float v = g_agg[(size_t)n * FDIM + c] + g_H[(size_t)n * FDIM + c];
    v = (v > 0.f) ? v : expm1f(v);
    float s = v, ss = v * v;
#pragma unroll
    for (int o = 16; o; o >>= 1) {
        s  += __shfl_xor_sync(0xffffffffu, s, o);
        ss += __shfl_xor_sync(0xffffffffu, ss, o);
    }
    float mu  = s * (1.f / HD);
    float var = ss * (1.f / HD) - mu * mu;
    float nrm = (v - mu) * rsqrtf(var + LN_EPS) * gamma[c] + beta[c];
    __shared__ float sm[FDIM];
    sm[c] = nrm;
    __syncthreads();
    if (threadIdx.x < HD) {
        float m = 0.f;
#pragma unroll
        for (int h = 0; h < HEADS; h++) m += sm[h * HD + lane];
        g_mean[(size_t)n * HD + lane] = m * (1.f / HEADS);
    }
}

// ---------------- K7: out = ELU(mean @ Wout + bout) -------------------------
__global__ void k_out(const float* __restrict__ Wout,
                      const float* __restrict__ bout,
                      float* __restrict__ out, int N) {
    __shared__ float sm[32][33];
    int row0 = blockIdx.x * 32;
    int tid  = threadIdx.x;
    for (int i = tid; i < 1024; i += 256) {
        int r = i >> 5, d = i & 31;
        sm[r][d] = (row0 + r < N) ? g_mean[(size_t)(row0 + r) * HD + d] : 0.f;
    }
    __syncthreads();
    int col = tid;
    float w[32];
#pragma unroll
    for (int d = 0; d < 32; d++) w[d] = Wout[d * FDIM + col];
    float b = bout[col];
    for (int r = 0; r < 32; r++) {
        if (row0 + r >= N) break;
        float acc = b;
#pragma unroll
        for (int d = 0; d < 32; d++) acc += sm[r][d] * w[d];
        acc = (acc > 0.f) ? acc : expm1f(acc);
        out[(size_t)(row0 + r) * FDIM + col] = acc;
    }
}

// ---------------- launch -----------------------------------------------------
extern "C" void kernel_launch(void* const* d_in, const int* in_sizes, int n_in,
                              void* d_out, int out_size) {
    const float* X    = (const float*)d_in[0];
    const int*   EI   = (const int*)  d_in[1];
    const float* W    = (const float*)d_in[2];
    const float* bw   = (const float*)d_in[3];
    const float* A    = (const float*)d_in[4];
    const float* ba   = (const float*)d_in[5];
    const float* gmm  = (const float*)d_in[6];
    const float* bet  = (const float*)d_in[7];
    const float* Wout = (const float*)d_in[8];
    const float* bout = (const float*)d_in[9];
    float* out = (float*)d_out;

    const int N = in_sizes[0] / FDIM;
    const int E = in_sizes[1] / 2;

    // K0: zero scratch
    k_init<<<(N * FDIM + 255) / 256, 256>>>(N);
    // K1: feature GEMM
    {
        dim3 grid(FDIM / 128, (N + 127) / 128);
        k_gemm_h<<<grid, 256>>>(X, W, bw, N);
    }
    // K2: attention pre-scores
    k_scores<<<N, 256>>>(A, N);
    // K3: edge scores + segment max
    k_edge_max<<<(E * HEADS + 255) / 256, 256>>>(EI, ba, E);
    // K4: exp + segment sum
    k_edge_exp<<<(E * HEADS + 255) / 256, 256>>>(EI, E);
    // K5: weighted scatter (warp per edge)
    k_edge_agg<<<(E + 7) / 8, 256>>>(EI, E);
    // K6: skip + ELU + LN + head mean
    k_node<<<N, 256>>>(gmm, bet, N);
    // K7: final projection + ELU
    k_out<<<(N + 31) / 32, 256>>>(Wout, bout, out, N);
}